// round 1
// baseline (speedup 1.0000x reference)
#include <cuda_runtime.h>
#include <math.h>

#define BROWS 16
#define NSAMP 524288
#define NG (NSAMP / 4)      // 131072 float4 groups per row
#define DEPTH 16            // prefetch ring depth (groups = 64 samples ahead)

// scratch (allocation-free rule: __device__ globals)
__device__ float g_v[BROWS * NSAMP];  // q * x_L, tiled: float4 index = n4*16 + b
__device__ float g_w[BROWS * NSAMP];  // w = u + v_next (y_L = q*w), same tiling

__device__ __forceinline__ float sanitize(float v) {
    if (isnan(v)) v = 0.0f;
    if (v == 0.0f) v = 1e-10f;
    return v;
}

struct RowP {
    float aA, aR, q, thr, ratio, invr, knee, gmk;
};

__device__ __forceinline__ RowP row_params(const float* __restrict__ p, int b) {
    float p0 = sanitize(p[b * 6 + 0]);
    float p1 = sanitize(p[b * 6 + 1]);
    float p2 = sanitize(p[b * 6 + 2]);
    float p3 = sanitize(p[b * 6 + 3]);
    float p4 = sanitize(p[b * 6 + 4]);
    float p5 = sanitize(p[b * 6 + 5]);
    RowP r;
    r.thr = -p0 * 60.0f;
    r.ratio = p1 * 10.0f;
    r.invr = 1.0f / r.ratio;
    float attack  = fmaxf(p2 / 10.0f, 1e-4f);
    float release = fmaxf(p3 * 3.0f, 0.005f);
    const float L9 = 2.1972245773362196f;
    r.aA = expf(-L9 / (44100.0f * attack));
    r.aR = expf(-L9 / (44100.0f * release));
    r.q = (r.aA <= r.aR) ? 1.0f : -1.0f;
    r.knee = p4 * 24.0f;
    float mk = p5 * 20.0f;
    r.gmk = exp10f(mk / 20.0f);
    return r;
}

// static gain curve -> x_L (gain reduction target, dB), exactly as reference
__device__ __forceinline__ float xl_of(float xi, const RowP& r) {
    float ax = fabsf(xi) + 1e-8f;
    float xg = 20.0f * log10f(ax);
    xg = fmaxf(xg, -96.0f);
    float d = xg - r.thr;
    float td = 2.0f * d;
    float xl;
    if (td < -r.knee) {
        xl = 0.0f;                          // y_G = x_G
    } else if (td > r.knee) {
        xl = d - d / r.ratio;               // y_G = thr + d/ratio
    } else {
        float h = (d + r.knee) * 0.5f;
        xl = -(r.invr * h * h) / (2.0f * r.knee);  // y_knee = x_G + invr*h^2/(2k)
    }
    return xl;
}

// ---------------- Kernel A: parallel x_L -> v = q*x_L (tiled transpose) -----
__global__ void k_xl(const float* __restrict__ x, const float* __restrict__ p) {
    int tid = blockIdx.x * blockDim.x + threadIdx.x;
    if (tid >= BROWS * NG) return;
    int b = tid / NG;
    int n4 = tid % NG;
    RowP r = row_params(p, b);
    float4 xv = reinterpret_cast<const float4*>(x)[b * NG + n4];
    float4 v;
    v.x = r.q * xl_of(xv.x, r);
    v.y = r.q * xl_of(xv.y, r);
    v.z = r.q * xl_of(xv.z, r);
    v.w = r.q * xl_of(xv.w, r);
    reinterpret_cast<float4*>(g_v)[n4 * BROWS + b] = v;
}

// ---------------- Kernel B: serial scan, 1 warp, 16 lanes -------------------
#define STEP(C)                                                        \
    do {                                                               \
        float c_ = (C);                                                \
        u = fmaxf(fmaf(aA, u, c_), fmaf(aR, u, c_));                   \
    } while (0)

__global__ void k_scan(const float* __restrict__ p) {
    int b = threadIdx.x;  // 0..15, one lane per row
    RowP r = row_params(p, b);
    float aA = r.aA, aR = r.aR;

    const float4* V = reinterpret_cast<const float4*>(g_v);
    float4* W = reinterpret_cast<float4*>(g_w);

    float4 ring[DEPTH];
#pragma unroll
    for (int i = 0; i < DEPTH; ++i) ring[i] = V[i * BROWS + b];

    float4 cur = ring[0];
    float u = -cur.y;  // u_0 = q*(y_0 - xl_1) = -v[1]

    // group 0: n = 0 (y_L=0 placeholder), steps n = 1,2,3
    {
        float4 nxt = ring[1];
        float4 w;
        w.x = 0.0f;
        STEP(cur.y - cur.z); w.y = u + cur.z;
        STEP(cur.z - cur.w); w.z = u + cur.w;
        STEP(cur.w - nxt.x); w.w = u + nxt.x;
        W[b] = w;
        ring[0] = V[DEPTH * BROWS + b];  // prefetch group 16 -> slot 0
        cur = nxt;
    }

    int gb = 1;
    // main loop: unrolled by DEPTH so ring indices are compile-time (regs)
    for (; gb + DEPTH <= NG - 1; gb += DEPTH) {
#pragma unroll
        for (int j = 0; j < DEPTH; ++j) {
            int g = gb + j;                     // gb ≡ 1 (mod 16)
            float4 nxt = ring[(j + 2) & (DEPTH - 1)];   // group g+1
            int pg = g + DEPTH;
            pg = (pg < NG) ? pg : (NG - 1);
            ring[(j + 1) & (DEPTH - 1)] = V[pg * BROWS + b];  // prefetch g+16
            float4 w;
            STEP(cur.x - cur.y); w.x = u + cur.y;
            STEP(cur.y - cur.z); w.y = u + cur.z;
            STEP(cur.z - cur.w); w.z = u + cur.w;
            STEP(cur.w - nxt.x); w.w = u + nxt.x;
            W[g * BROWS + b] = w;
            cur = nxt;
        }
    }

    // tail groups with direct loads (latency-exposed but only <=15 groups)
    for (int g = gb; g <= NG - 2; ++g) {
        float4 nxt = V[(g + 1) * BROWS + b];
        float4 w;
        STEP(cur.x - cur.y); w.x = u + cur.y;
        STEP(cur.y - cur.z); w.y = u + cur.z;
        STEP(cur.z - cur.w); w.z = u + cur.w;
        STEP(cur.w - nxt.x); w.w = u + nxt.x;
        W[g * BROWS + b] = w;
        cur = nxt;
    }

    // last group: v_N treated as 0 (w_{N-1} = u_{N-1})
    {
        float4 w;
        STEP(cur.x - cur.y); w.x = u + cur.y;
        STEP(cur.y - cur.z); w.y = u + cur.z;
        STEP(cur.z - cur.w); w.z = u + cur.w;
        STEP(cur.w);         w.w = u;
        W[(NG - 1) * BROWS + b] = w;
    }
}

// ---------------- Kernel C: parallel output --------------------------------
__device__ __forceinline__ float drc_out(float xi, float wi, const RowP& r) {
    float y = fmaxf(r.q * wi, -96.0f);                 // clip(y_L, -96)
    float val = xi * exp10f(-y / 20.0f) * r.gmk;
    return isfinite(val) ? val : 0.0f;
}

__global__ void k_out(const float* __restrict__ x, const float* __restrict__ p,
                      float* __restrict__ out) {
    int tid = blockIdx.x * blockDim.x + threadIdx.x;
    if (tid >= BROWS * NG) return;
    int b = tid / NG;
    int n4 = tid % NG;
    RowP r = row_params(p, b);
    float4 w = reinterpret_cast<const float4*>(g_w)[n4 * BROWS + b];
    float4 xv = reinterpret_cast<const float4*>(x)[b * NG + n4];
    float4 o;
    o.x = drc_out(xv.x, w.x, r);
    o.y = drc_out(xv.y, w.y, r);
    o.z = drc_out(xv.z, w.z, r);
    o.w = drc_out(xv.w, w.w, r);
    reinterpret_cast<float4*>(out)[b * NG + n4] = o;
}

extern "C" void kernel_launch(void* const* d_in, const int* in_sizes, int n_in,
                              void* d_out, int out_size) {
    const float* x = (const float*)d_in[0];      // [16, 524288] f32
    const float* p = (const float*)d_in[1];      // [16, 6] f32
    float* out = (float*)d_out;                  // [16, 524288] f32

    int total = BROWS * NG;
    int threads = 256;
    int blocks = (total + threads - 1) / threads;

    k_xl<<<blocks, threads>>>(x, p);
    k_scan<<<1, 16>>>(p);
    k_out<<<blocks, threads>>>(x, p, out);
}